// round 6
// baseline (speedup 1.0000x reference)
#include <cuda_runtime.h>
#include <math.h>

#define BATCH 8
#define SEQ 512
#define HID 768
#define NHEAD 12
#define DHEAD 64
#define NLAYER 12
#define FFDIM 3072
#define SPAN 256
#define TSPAN 512
#define EPS 1e-7f

// ---------------- scratch (static device globals; no allocs allowed) ----------------
__device__ float g_h  [BATCH*SEQ*HID];
__device__ float g_q  [BATCH*SEQ*HID];
__device__ float g_k  [BATCH*SEQ*HID];
__device__ float g_v  [BATCH*SEQ*HID];
__device__ float g_tmp[BATCH*SEQ*HID];
__device__ float g_h1 [BATCH*SEQ*HID];
__device__ float g_ctx[BATCH*SEQ*HID];
__device__ float g_ff [BATCH*SEQ*FFDIM];
__device__ float g_qk [(size_t)BATCH*NHEAD*SEQ*SEQ];
__device__ float g_c2p[(size_t)BATCH*NHEAD*SEQ*TSPAN];   // [q, m] per (b,h)
__device__ float g_p2c[(size_t)BATCH*NHEAD*TSPAN*SEQ];   // TRANSPOSED: [m, k] per (b,h)
__device__ float g_posk[TSPAN*HID];
__device__ float g_posq[TSPAN*HID];
__device__ int   g_c2pidx[SEQ*SEQ];   // p2cidx[k,q] == c2pidx[q,k] (DeBERTa identity)

// ---------------- tf32 helpers ----------------
__device__ __forceinline__ unsigned f2tf32(float x) {
    unsigned r;
    asm("cvt.rna.tf32.f32 %0, %1;" : "=r"(r) : "f"(x));
    return r;
}

__device__ __forceinline__ void mma8(float* c, const unsigned* a, const unsigned* b) {
    asm volatile(
        "mma.sync.aligned.m16n8k8.row.col.f32.tf32.tf32.f32 "
        "{%0,%1,%2,%3},{%4,%5,%6,%7},{%8,%9},{%0,%1,%2,%3};"
        : "+f"(c[0]), "+f"(c[1]), "+f"(c[2]), "+f"(c[3])
        : "r"(a[0]), "r"(a[1]), "r"(a[2]), "r"(a[3]), "r"(b[0]), "r"(b[1]));
}

// ---------------- relative position bucketing ----------------
__global__ void build_idx_kernel() {
    int idx = blockIdx.x * blockDim.x + threadIdx.x;
    if (idx >= SEQ * SEQ) return;
    int q = idx / SEQ, k = idx % SEQ;
    int rel = q - k;
    const int mid = SPAN / 2;  // 128
    int sgn = (rel > 0) - (rel < 0);
    double abs_pos = (rel < mid && rel > -mid) ? (double)(mid - 1) : (double)abs(rel);
    int bucket;
    if (abs_pos <= (double)mid) {
        bucket = rel;
    } else {
        double lp = ceil(log(abs_pos / (double)mid) / log(511.0 / (double)mid) * (double)(mid - 1))
                    + (double)mid;
        bucket = (int)(lp * (double)sgn);
    }
    int c2p = bucket + SPAN;  c2p = min(max(c2p, 0), TSPAN - 1);
    g_c2pidx[idx] = c2p;
}

// ---------------- embedding gather ----------------
__global__ void embed_kernel(const float* __restrict__ we, const float* __restrict__ pe,
                             const int* __restrict__ ids, float* __restrict__ out) {
    long i = (long)blockIdx.x * blockDim.x + threadIdx.x;
    if (i >= (long)BATCH * SEQ * HID) return;
    int c = (int)(i % HID);
    long t = i / HID;
    int s = (int)(t % SEQ);
    out[i] = we[(long)ids[t] * HID + c] + pe[(long)s * HID + c];
}

// ---------------- LayerNorm (optional residual, optional mask scaling) ----------------
__global__ __launch_bounds__(256) void ln_kernel(
    const float* __restrict__ x, const float* __restrict__ res,
    const float* __restrict__ g, const float* __restrict__ bta,
    const int* __restrict__ mask, float* __restrict__ out)
{
    int t = blockIdx.x;
    int tid = threadIdx.x;
    __shared__ float sh[HID];
    __shared__ float sred[8];
    __shared__ float s_mu, s_rstd;

    const float* xp = x + (long)t * HID;
    const float* rp = res ? (res + (long)t * HID) : nullptr;

    float s = 0.f;
    for (int i = tid; i < HID; i += 256) {
        float v = xp[i] + (rp ? rp[i] : 0.f);
        sh[i] = v;
        s += v;
    }
    #pragma unroll
    for (int o = 16; o > 0; o >>= 1) s += __shfl_xor_sync(0xffffffffu, s, o);
    if ((tid & 31) == 0) sred[tid >> 5] = s;
    __syncthreads();
    if (tid == 0) {
        float tt = 0.f;
        #pragma unroll
        for (int i = 0; i < 8; i++) tt += sred[i];
        s_mu = tt / (float)HID;
    }
    __syncthreads();
    float mu = s_mu;

    float vs = 0.f;
    for (int i = tid; i < HID; i += 256) { float d = sh[i] - mu; vs += d * d; }
    #pragma unroll
    for (int o = 16; o > 0; o >>= 1) vs += __shfl_xor_sync(0xffffffffu, vs, o);
    if ((tid & 31) == 0) sred[tid >> 5] = vs;
    __syncthreads();
    if (tid == 0) {
        float tt = 0.f;
        #pragma unroll
        for (int i = 0; i < 8; i++) tt += sred[i];
        s_rstd = 1.0f / sqrtf(tt / (float)HID + EPS);
    }
    __syncthreads();
    float rstd = s_rstd;
    float mscale = mask ? (float)mask[t] : 1.0f;

    float* op = out + (long)t * HID;
    for (int i = tid; i < HID; i += 256)
        op[i] = ((sh[i] - mu) * rstd * g[i] + bta[i]) * mscale;
}

// ---------------- dense GEMM via 3xTF32 tensor cores ----------------
// C[M,N] = A[M,K] @ B[K,N] + bias, optional exact GELU.
// 128x128 CTA tile, 256 threads = 8 warps (2x4), warp tile 64x32 (4x4 mma tiles of 16x8),
// K-tile 16 (two k8 steps), hi/lo tf32 split: acc += Ah*Bh + Ah*Bl + Al*Bh.
// Smem row stride 136 floats -> fragment loads are bank-conflict-free (bank = 8q+g).
__device__ __forceinline__ void tf32_gemm_tile(
    const float* __restrict__ A, const float* __restrict__ B,
    const float* __restrict__ bias, float* __restrict__ C,
    int N, int K, int fuse_gelu, int bx, int by,
    float Ah[16][136], float Al[16][136], float Bh[16][136], float Bl[16][136])
{
    int tid = threadIdx.x;
    int lane = tid & 31;
    int warp = tid >> 5;
    int warpM = warp >> 2;       // 0..1
    int warpN = warp & 3;        // 0..3
    int g = lane >> 2;           // 0..7
    int qd = lane & 3;           // 0..3

    int aRow = tid >> 1;               // 0..127
    int aCol = (tid & 1) << 3;         // 0 or 8
    int bRow = tid >> 4;               // 0..15
    int bCol = (tid & 15) << 3;        // 0..120

    const float* Ap = A + (long)(by * 128 + aRow) * K + aCol;
    const float* Bp = B + (long)bRow * N + bx * 128 + bCol;

    float acc[4][4][4];  // [mt][nt][frag]
    #pragma unroll
    for (int mt = 0; mt < 4; mt++)
        #pragma unroll
        for (int nt = 0; nt < 4; nt++)
            #pragma unroll
            for (int f = 0; f < 4; f++) acc[mt][nt][f] = 0.f;

    // preload tile 0 into registers
    float4 ra0 = *(const float4*)(Ap);
    float4 ra1 = *(const float4*)(Ap + 4);
    float4 rb0 = *(const float4*)(Bp);
    float4 rb1 = *(const float4*)(Bp + 4);

    for (int k0 = 0; k0 < K; k0 += 16) {
        // convert + store current tile
        {
            float av[8] = {ra0.x, ra0.y, ra0.z, ra0.w, ra1.x, ra1.y, ra1.z, ra1.w};
            float bv[8] = {rb0.x, rb0.y, rb0.z, rb0.w, rb1.x, rb1.y, rb1.z, rb1.w};
            #pragma unroll
            for (int j = 0; j < 8; j++) {
                unsigned hb = f2tf32(av[j]);
                float hf = __uint_as_float(hb);
                Ah[aCol + j][aRow] = hf;
                Al[aCol + j][aRow] = __uint_as_float(f2tf32(av[j] - hf));
                unsigned hb2 = f2tf32(bv[j]);
                float hf2 = __uint_as_float(hb2);
                Bh[bRow][bCol + j] = hf2;
                Bl[bRow][bCol + j] = __uint_as_float(f2tf32(bv[j] - hf2));
            }
        }
        __syncthreads();

        // prefetch next tile
        int more = (k0 + 16) < K;
        if (more) {
            ra0 = *(const float4*)(Ap + k0 + 16);
            ra1 = *(const float4*)(Ap + k0 + 20);
            rb0 = *(const float4*)(Bp + (long)(k0 + 16) * N);
            rb1 = *(const float4*)(Bp + (long)(k0 + 16) * N + 4);
        }

        #pragma unroll
        for (int c = 0; c < 16; c += 8) {
            // B fragments for all 4 n-tiles, hi+lo planes
            unsigned bh[4][2], bl[4][2];
            #pragma unroll
            for (int nt = 0; nt < 4; nt++) {
                int n0 = warpN * 32 + nt * 8 + g;
                bh[nt][0] = __float_as_uint(Bh[c + qd][n0]);
                bh[nt][1] = __float_as_uint(Bh[c + qd + 4][n0]);
                bl[nt][0] = __float_as_uint(Bl[c + qd][n0]);
                bl[nt][1] = __float_as_uint(Bl[c + qd + 4][n0]);
            }
            #pragma unroll
            for (int mt = 0; mt < 4; mt++) {
                int m0 = warpM * 64 + mt * 16;
                unsigned ah[4], al[4];
                ah[0] = __float_as_uint(Ah[c + qd][m0 + g]);
                ah[1] = __float_as_uint(Ah[c + qd][m0 + g + 8]);
                ah[2] = __float_as_uint(Ah[c + qd + 4][m0 + g]);
                ah[3] = __float_as_uint(Ah[c + qd + 4][m0 + g + 8]);
                al[0] = __float_as_uint(Al[c + qd][m0 + g]);
                al[1] = __float_as_uint(Al[c + qd][m0 + g + 8]);
                al[2] = __float_as_uint(Al[c + qd + 4][m0 + g]);
                al[3] = __float_as_uint(Al[c + qd + 4][m0 + g + 8]);
                #pragma unroll
                for (int nt = 0; nt < 4; nt++) {
                    mma8(acc[mt][nt], ah, bh[nt]);
                    mma8(acc[mt][nt], ah, bl[nt]);
                    mma8(acc[mt][nt], al, bh[nt]);
                }
            }
        }
        __syncthreads();
    }

    // epilogue: bias (+gelu), write float2 pairs
    #pragma unroll
    for (int mt = 0; mt < 4; mt++) {
        int r0 = by * 128 + warpM * 64 + mt * 16 + g;
        int r1 = r0 + 8;
        #pragma unroll
        for (int nt = 0; nt < 4; nt++) {
            int col = bx * 128 + warpN * 32 + nt * 8 + 2 * qd;
            float b0 = bias[col], b1 = bias[col + 1];
            float v[4];
            v[0] = acc[mt][nt][0] + b0;
            v[1] = acc[mt][nt][1] + b1;
            v[2] = acc[mt][nt][2] + b0;
            v[3] = acc[mt][nt][3] + b1;
            if (fuse_gelu) {
                #pragma unroll
                for (int f = 0; f < 4; f++)
                    v[f] = 0.5f * v[f] * (1.0f + erff(v[f] * 0.70710678118654752440f));
            }
            *(float2*)(C + (long)r0 * N + col) = make_float2(v[0], v[1]);
            *(float2*)(C + (long)r1 * N + col) = make_float2(v[2], v[3]);
        }
    }
}

__global__ __launch_bounds__(256) void sgemm_kernel(
    const float* __restrict__ A, const float* __restrict__ B,
    const float* __restrict__ bias, float* __restrict__ C,
    int N, int K, int fuse_gelu)
{
    __shared__ float Ah[16][136], Al[16][136], Bh[16][136], Bl[16][136];
    tf32_gemm_tile(A, B, bias, C, N, K, fuse_gelu, blockIdx.x, blockIdx.y, Ah, Al, Bh, Bl);
}

// fused triple-GEMM (same A, operands selected by blockIdx.z)
__global__ __launch_bounds__(256) void sgemm3_kernel(
    const float* __restrict__ A,
    const float* __restrict__ W0, const float* __restrict__ W1, const float* __restrict__ W2,
    const float* __restrict__ b0, const float* __restrict__ b1, const float* __restrict__ b2,
    float* __restrict__ C0, float* __restrict__ C1, float* __restrict__ C2,
    int N, int K)
{
    __shared__ float Ah[16][136], Al[16][136], Bh[16][136], Bl[16][136];
    const float* W = (blockIdx.z == 0) ? W0 : (blockIdx.z == 1) ? W1 : W2;
    const float* bb = (blockIdx.z == 0) ? b0 : (blockIdx.z == 1) ? b1 : b2;
    float* C = (blockIdx.z == 0) ? C0 : (blockIdx.z == 1) ? C1 : C2;
    tf32_gemm_tile(A, W, bb, C, N, K, 0, blockIdx.x, blockIdx.y, Ah, Al, Bh, Bl);
}

// ---------------- fused score GEMMs: C[i,j] = A_row_i . B_row_j over K=64 ----------------
// 128x128 tile, 256 threads, 8x8 acc, K=64 in two 32-chunks.
//   mode 0: A = q[b,h],  B = k[b,h]   -> g_qk  [SEQ,SEQ]
//   mode 1: A = q[b,h],  B = posk[h]  -> g_c2p [SEQ,TSPAN]
//   mode 2: A = posq[h], B = k[b,h]   -> g_p2c [TSPAN,SEQ] (transposed p2c)
__global__ __launch_bounds__(256) void gemm_scores_kernel(
    const float* __restrict__ q, const float* __restrict__ k,
    const float* __restrict__ posk, const float* __restrict__ posq)
{
    const int NB = BATCH * NHEAD;
    int z = blockIdx.z;
    int mode = z / NB;
    int batch = z % NB;
    int b = batch / NHEAD, h = batch % NHEAD;

    const float* Ab;
    const float* Bb;
    float* Cb;
    if (mode == 0) {
        Ab = q + (long)b * SEQ * HID + h * DHEAD;
        Bb = k + (long)b * SEQ * HID + h * DHEAD;
        Cb = g_qk + (long)batch * SEQ * SEQ;
    } else if (mode == 1) {
        Ab = q + (long)b * SEQ * HID + h * DHEAD;
        Bb = posk + h * DHEAD;
        Cb = g_c2p + (long)batch * SEQ * TSPAN;
    } else {
        Ab = posq + h * DHEAD;
        Bb = k + (long)b * SEQ * HID + h * DHEAD;
        Cb = g_p2c + (long)batch * TSPAN * SEQ;
    }

    __shared__ float As[32][132];
    __shared__ float Bs[32][132];
    int tid = threadIdx.x;
    int tx = tid & 15, ty = tid >> 4;
    int bx = blockIdx.x, by = blockIdx.y;

    float acc[8][8];
    #pragma unroll
    for (int i = 0; i < 8; i++)
        #pragma unroll
        for (int j = 0; j < 8; j++) acc[i][j] = 0.f;

    #pragma unroll
    for (int c = 0; c < 2; c++) {
        __syncthreads();
        #pragma unroll
        for (int it = 0; it < 4; it++) {
            int e = tid + 256 * it;
            int m = e >> 3;            // 0..127
            int kg = (e & 7) << 2;     // 0..28
            float4 a4 = *(const float4*)(Ab + (long)(by * 128 + m) * HID + c * 32 + kg);
            As[kg + 0][m] = a4.x; As[kg + 1][m] = a4.y;
            As[kg + 2][m] = a4.z; As[kg + 3][m] = a4.w;
            float4 b4 = *(const float4*)(Bb + (long)(bx * 128 + m) * HID + c * 32 + kg);
            Bs[kg + 0][m] = b4.x; Bs[kg + 1][m] = b4.y;
            Bs[kg + 2][m] = b4.z; Bs[kg + 3][m] = b4.w;
        }
        __syncthreads();
        #pragma unroll
        for (int kk = 0; kk < 32; kk++) {
            float ar[8], br[8];
            *(float4*)(ar)     = *(const float4*)&As[kk][ty * 8];
            *(float4*)(ar + 4) = *(const float4*)&As[kk][ty * 8 + 4];
            *(float4*)(br)     = *(const float4*)&Bs[kk][tx * 8];
            *(float4*)(br + 4) = *(const float4*)&Bs[kk][tx * 8 + 4];
            #pragma unroll
            for (int i = 0; i < 8; i++)
                #pragma unroll
                for (int j = 0; j < 8; j++) acc[i][j] += ar[i] * br[j];
        }
    }

    #pragma unroll
    for (int i = 0; i < 8; i++) {
        int row = by * 128 + ty * 8 + i;
        #pragma unroll
        for (int jj = 0; jj < 8; jj += 4) {
            int col = bx * 128 + tx * 8 + jj;
            *(float4*)(Cb + (long)row * 512 + col) = *(float4*)&acc[i][jj];
        }
    }
}

// ---------------- fused gather + mask + softmax (in place over g_qk) ----------------
// scores[q,k] = (qk[q,k] + c2p[q, idx] + p2cT[idx, k]) / sqrt(3*DH), idx = c2pidx[q,k]
__global__ __launch_bounds__(256) void softmax_kernel(const int* __restrict__ mask)
{
    int q = blockIdx.x, h = blockIdx.y, b = blockIdx.z;
    long base  = ((long)(b * NHEAD + h) * SEQ + q) * SEQ;
    long cbase = ((long)(b * NHEAD + h) * SEQ + q) * TSPAN;
    long pbase = (long)(b * NHEAD + h) * TSPAN * SEQ;
    int tid = threadIdx.x;
    const float invScale = 0.07216878364870322992f;  // 1/sqrt(3*DH)

    __shared__ float sred[8];
    __shared__ float s_max, s_sum;

    int mrow = mask[b * SEQ + q];
    float vals[2];
    int vmask[2];
    #pragma unroll
    for (int u = 0; u < 2; u++) {
        int k = tid + u * 256;
        int idx = g_c2pidx[q * SEQ + k];   // shared index (p2cidx = c2pidx^T)
        float s = g_qk[base + k]
                + g_c2p[cbase + idx]
                + g_p2c[pbase + (long)idx * SEQ + k];   // transposed p2c: coalesced in k
        s *= invScale;
        int valid = mrow && mask[b * SEQ + k];
        vmask[u] = valid;
        vals[u] = valid ? s : -3.402823466e38f;
    }

    float mx = fmaxf(vals[0], vals[1]);
    #pragma unroll
    for (int o = 16; o > 0; o >>= 1) mx = fmaxf(mx, __shfl_xor_sync(0xffffffffu, mx, o));
    if ((tid & 31) == 0) sred[tid >> 5] = mx;
    __syncthreads();
    if (tid == 0) {
        float t = sred[0];
        #pragma unroll
        for (int i = 1; i < 8; i++) t = fmaxf(t, sred[i]);
        s_max = t;
    }
    __syncthreads();
    mx = s_max;

    float p[2];
    float sum = 0.f;
    #pragma unroll
    for (int u = 0; u < 2; u++) {
        p[u] = vmask[u] ? expf(vals[u] - mx) : 0.f;
        sum += p[u];
    }
    #pragma unroll
    for (int o = 16; o > 0; o >>= 1) sum += __shfl_xor_sync(0xffffffffu, sum, o);
    if ((tid & 31) == 0) sred[tid >> 5] = sum;
    __syncthreads();
    if (tid == 0) {
        float t = 0.f;
        #pragma unroll
        for (int i = 0; i < 8; i++) t += sred[i];
        s_sum = t;
    }
    __syncthreads();
    float inv = s_sum > 0.f ? 1.0f / s_sum : 0.f;

    #pragma unroll
    for (int u = 0; u < 2; u++)
        g_qk[base + tid + u * 256] = p[u] * inv;
}

// ---------------- batched probs @ V:  O[b,h] = P[b,h] [S,S] @ V[b,h] [S,DH] ----------------
// 128x64 tile, 128 threads, 8x8 acc, K chunks of 16.
__global__ __launch_bounds__(128) void gemm_pv_kernel(
    const float* __restrict__ P, const float* __restrict__ V, float* __restrict__ O)
{
    int batch = blockIdx.z;
    int b = batch / NHEAD, h = batch % NHEAD;
    const float* Pb = P + (long)batch * SEQ * SEQ;
    const float* Vb = V + (long)b * SEQ * HID + h * DHEAD;
    float* Ob = O + (long)b * SEQ * HID + h * DHEAD;
    int by = blockIdx.x;

    __shared__ float Ps[16][132];
    __shared__ float Vs[16][68];
    int tid = threadIdx.x;
    int tx = tid & 7;        // 8 col groups of 8 -> 64 cols
    int ty = tid >> 3;       // 16 row groups of 8 -> 128 rows

    float acc[8][8];
    #pragma unroll
    for (int i = 0; i < 8; i++)
        #pragma unroll
        for (int j = 0; j < 8; j++) acc[i][j] = 0.f;

    for (int k0 = 0; k0 < SEQ; k0 += 16) {
        __syncthreads();
        #pragma unroll
        for (int it = 0; it < 4; it++) {
            int e = tid + 128 * it;    // 0..511
            int m = e >> 2;            // 0..127
            int kg = (e & 3) << 2;     // 0,4,8,12
            float4 p4 = *(const float4*)(Pb + (long)(by * 128 + m) * SEQ + k0 + kg);
            Ps[kg + 0][m] = p4.x; Ps[kg + 1][m] = p4.y;
            Ps[kg + 2][m] = p4.z; Ps[kg + 3][m] = p4.w;
        }
        #pragma unroll
        for (int it = 0; it < 2; it++) {
            int e = tid + 128 * it;    // 0..255
            int r = e >> 4;            // 0..15
            int cg = (e & 15) << 2;    // 0..60
            float4 v4 = *(const float4*)(Vb + (long)(k0 + r) * HID + cg);
            *(float4*)&Vs[r][cg] = v4;
        }
        __syncthreads();
        #pragma unroll
        for (int kk = 0; kk < 16; kk++) {
            float ar[8], br[8];
            *(float4*)(ar)     = *(const float4*)&Ps[kk][ty * 8];
            *(float4*)(ar + 4) = *(const float4*)&Ps[kk][ty * 8 + 4];
            *(float4*)(br)     = *(const float4*)&Vs[kk][tx * 8];
            *(float4*)(br + 4) = *(const float4*)&Vs[kk][tx * 8 + 4];
            #pragma unroll
            for (int i = 0; i < 8; i++)
                #pragma unroll
                for (int j = 0; j < 8; j++) acc[i][j] += ar[i] * br[j];
        }
    }

    #pragma unroll
    for (int i = 0; i < 8; i++) {
        int row = by * 128 + ty * 8 + i;
        #pragma unroll
        for (int jj = 0; jj < 8; jj += 4)
            *(float4*)(Ob + (long)row * HID + tx * 8 + jj) = *(float4*)&acc[i][jj];
    }
}

// ---------------- host orchestration ----------------
extern "C" void kernel_launch(void* const* d_in, const int* in_sizes, int n_in,
                              void* d_out, int out_size)
{
    const float* word_emb = (const float*)d_in[0];
    const float* pos_emb  = (const float*)d_in[1];
    const float* emb_ln_g = (const float*)d_in[2];
    const float* emb_ln_b = (const float*)d_in[3];
    const float* rel_emb  = (const float*)d_in[4];
    const float* Wq = (const float*)d_in[5];
    const float* bq = (const float*)d_in[6];
    const float* Wk = (const float*)d_in[7];
    const float* bk = (const float*)d_in[8];
    const float* Wv = (const float*)d_in[9];
    const float* bv = (const float*)d_in[10];
    const float* Wo = (const float*)d_in[11];
    const float* bo = (const float*)d_in[12];
    const float* ln1_g = (const float*)d_in[13];
    const float* ln1_b = (const float*)d_in[14];
    const float* Wi  = (const float*)d_in[15];
    const float* bi  = (const float*)d_in[16];
    const float* Wo2 = (const float*)d_in[17];
    const float* bo2 = (const float*)d_in[18];
    const float* ln2_g = (const float*)d_in[19];
    const float* ln2_b = (const float*)d_in[20];
    const int* input_ids = (const int*)d_in[21];
    const int* amask     = (const int*)d_in[22];
    float* out = (float*)d_out;

    float *p_h, *p_q, *p_k, *p_v, *p_tmp, *p_h1, *p_ctx, *p_ff, *p_qk, *p_posk, *p_posq;
    cudaGetSymbolAddress((void**)&p_h,   g_h);
    cudaGetSymbolAddress((void**)&p_q,   g_q);
    cudaGetSymbolAddress((void**)&p_k,   g_k);
    cudaGetSymbolAddress((void**)&p_v,   g_v);
    cudaGetSymbolAddress((void**)&p_tmp, g_tmp);
    cudaGetSymbolAddress((void**)&p_h1,  g_h1);
    cudaGetSymbolAddress((void**)&p_ctx, g_ctx);
    cudaGetSymbolAddress((void**)&p_ff,  g_ff);
    cudaGetSymbolAddress((void**)&p_qk,  g_qk);
    cudaGetSymbolAddress((void**)&p_posk, g_posk);
    cudaGetSymbolAddress((void**)&p_posq, g_posq);

    const int BS = BATCH * SEQ;  // 4096

    build_idx_kernel<<<(SEQ * SEQ + 255) / 256, 256>>>();
    embed_kernel<<<(BS * HID + 255) / 256, 256>>>(word_emb, pos_emb, input_ids, p_tmp);
    ln_kernel<<<BS, 256>>>(p_tmp, nullptr, emb_ln_g, emb_ln_b, amask, p_h);

    for (int l = 0; l < NLAYER; l++) {
        const float* Wq_l = Wq + (long)l * HID * HID;  const float* bq_l = bq + l * HID;
        const float* Wk_l = Wk + (long)l * HID * HID;  const float* bk_l = bk + l * HID;
        const float* Wv_l = Wv + (long)l * HID * HID;  const float* bv_l = bv + l * HID;
        const float* Wo_l = Wo + (long)l * HID * HID;  const float* bo_l = bo + l * HID;
        const float* Wi_l  = Wi  + (long)l * HID * FFDIM;  const float* bi_l  = bi  + l * FFDIM;
        const float* Wo2_l = Wo2 + (long)l * FFDIM * HID;  const float* bo2_l = bo2 + l * HID;

        // fused QKV projection (6 x 32 x 3 = 576 CTAs)
        dim3 gQKV(HID / 128, BS / 128, 3);
        sgemm3_kernel<<<gQKV, 256>>>(p_h, Wq_l, Wk_l, Wv_l, bq_l, bk_l, bv_l,
                                     p_q, p_k, p_v, HID, HID);

        // fused positional projections (z=0: posK, z=1: posQ)  (6 x 4 x 2 = 48 CTAs)
        dim3 gPos(HID / 128, TSPAN / 128, 2);
        sgemm3_kernel<<<gPos, 256>>>(rel_emb, Wk_l, Wq_l, Wq_l, bk_l, bq_l, bq_l,
                                     p_posk, p_posq, p_posq, HID, HID);

        // fused qk + c2p + p2c(transposed) score GEMMs: 4 x 4 x 288 CTAs
        dim3 gSc(4, 4, 3 * BATCH * NHEAD);
        gemm_scores_kernel<<<gSc, 256>>>(p_q, p_k, p_posk, p_posq);

        dim3 gSM(SEQ, NHEAD, BATCH);
        softmax_kernel<<<gSM, 256>>>(amask);

        dim3 gPV(4, 1, BATCH * NHEAD);
        gemm_pv_kernel<<<gPV, 128>>>(p_qk, p_v, p_ctx);

        dim3 gP(HID / 128, BS / 128);
        sgemm_kernel<<<gP, 256>>>(p_ctx, Wo_l, bo_l, p_tmp, HID, HID, 0);
        ln_kernel<<<BS, 256>>>(p_tmp, p_h, ln1_g + l * HID, ln1_b + l * HID, nullptr, p_h1);

        dim3 gFF(FFDIM / 128, BS / 128);     // (24, 32)
        sgemm_kernel<<<gFF, 256>>>(p_h1, Wi_l, bi_l, p_ff, FFDIM, HID, 1);

        dim3 gO2(HID / 128, BS / 128);       // (6, 32)
        sgemm_kernel<<<gO2, 256>>>(p_ff, Wo2_l, bo2_l, p_tmp, HID, FFDIM, 0);

        float* dst = (l == NLAYER - 1) ? out : p_h;
        ln_kernel<<<BS, 256>>>(p_tmp, p_h1, ln2_g + l * HID, ln2_b + l * HID, nullptr, dst);
    }
}